// round 5
// baseline (speedup 1.0000x reference)
#include <cuda_runtime.h>
#include <cuda_fp16.h>
#include <cstdint>

// Batched C[b,n,m] = sum_e A[b,n,e] * B[b,m,e]
// b=8, n=m=2048, e=1024, fp32 in/out.
// mma.sync m16n8k16 fp16 (fp32 accum), 128x256 CTA tile, 256 threads,
// 64x64 warp tiles, fp16 smem (producer-converted), 4-stage ring, BK=64.

#define TM 128
#define TN 256
#define BKH 64                  // K per chunk (halfs) -> 128B rows
#define NSTG 4
#define EDIM 1024
#define NDIM 2048
#define MDIM 2048
#define NB 8
#define NCHUNK (EDIM / BKH)     // 16
#define A_BYTES (TM * BKH * 2)  // 16384
#define B_BYTES (TN * BKH * 2)  // 32768
#define STG (A_BYTES + B_BYTES) // 49152
#define SMEM_BYTES (NSTG * STG) // 196608

__device__ __forceinline__ uint32_t packh2(float lo, float hi) {
    __half2 h = __floats2half2_rn(lo, hi);   // .x = lo half, .y = hi half
    return *(uint32_t*)&h;
}
__device__ __forceinline__ uint32_t ldsu(uint32_t a) {
    uint32_t v;
    asm volatile("ld.shared.b32 %0, [%1];" : "=r"(v) : "r"(a));
    return v;
}
__device__ __forceinline__ void sts128(uint32_t a, uint32_t p0, uint32_t p1,
                                       uint32_t p2, uint32_t p3) {
    asm volatile("st.shared.v4.b32 [%0], {%1,%2,%3,%4};"
                 :: "r"(a), "r"(p0), "r"(p1), "r"(p2), "r"(p3) : "memory");
}

// Convert one (row, 32-float k-segment): 8 LDG.128 -> 16 cvt.f16x2 -> 4 STS.128.
// Swizzle: 16B-chunk index XOR (row & 7); row stride 128B.
__device__ __forceinline__ void conv_unit(uint32_t rowbase, int key,
                                          const float* src, int k0) {
    float4 v[8];
    #pragma unroll
    for (int i = 0; i < 8; i++) v[i] = *(const float4*)(src + i * 4);
    #pragma unroll
    for (int j = 0; j < 4; j++) {
        uint32_t p0 = packh2(v[2*j].x,   v[2*j].y);
        uint32_t p1 = packh2(v[2*j].z,   v[2*j].w);
        uint32_t p2 = packh2(v[2*j+1].x, v[2*j+1].y);
        uint32_t p3 = packh2(v[2*j+1].z, v[2*j+1].w);
        sts128(rowbase + ((((k0 >> 3) + j) ^ key) * 16), p0, p1, p2, p3);
    }
}

__global__ __launch_bounds__(256, 1)
void bmm_f16_v4(const float* __restrict__ A, const float* __restrict__ B,
                float* __restrict__ C) {
    extern __shared__ char smem[];
    uint32_t sbase;
    asm("{ .reg .u64 t; cvta.to.shared.u64 t, %1; cvt.u32.u64 %0, t; }"
        : "=r"(sbase) : "l"(smem));

    const int tid  = threadIdx.x;
    const int warp = tid >> 5;
    const int lane = tid & 31;
    const int wm   = warp & 1;        // 2 row blocks of 64
    const int wn   = warp >> 1;       // 4 col blocks of 64
    const int g    = lane >> 2;       // 0..7
    const int t    = lane & 3;        // 0..3

    const int b = blockIdx.z, by = blockIdx.y, bx = blockIdx.x;
    const float* Ab = A + ((size_t)b * NDIM + (size_t)by * TM) * EDIM;
    const float* Bb = B + ((size_t)b * MDIM + (size_t)bx * TN) * EDIM;

    float acc[4][8][4];
    #pragma unroll
    for (int i = 0; i < 4; i++)
        #pragma unroll
        for (int j = 0; j < 8; j++)
            #pragma unroll
            for (int r = 0; r < 4; r++) acc[i][j][r] = 0.f;

    // Producer assignment: A = 256 units (row, 32-k half); B = 512 units.
    const int ra  = tid >> 1;               // A row 0..127
    const int ka  = (tid & 1) * 32;
    const int rb0 = tid >> 1;               // B rows 0..127
    const int rb1 = (tid + 256) >> 1;       // B rows 128..255
    const int kb0 = (tid & 1) * 32;

    #define PRODUCE(c) do {                                                   \
        uint32_t st = sbase + ((c) & (NSTG - 1)) * STG;                       \
        int kb = (c) * BKH;                                                   \
        conv_unit(st + ra * 128, ra & 7,                                      \
                  Ab + (size_t)ra * EDIM + kb + ka, ka);                      \
        conv_unit(st + A_BYTES + rb0 * 128, rb0 & 7,                          \
                  Bb + (size_t)rb0 * EDIM + kb + kb0, kb0);                   \
        conv_unit(st + A_BYTES + rb1 * 128, rb1 & 7,                          \
                  Bb + (size_t)rb1 * EDIM + kb + kb0, kb0);                   \
    } while (0)

    PRODUCE(0);
    PRODUCE(1);

    for (int c = 0; c < NCHUNK; c++) {
        if (c + 2 < NCHUNK) PRODUCE(c + 2);
        __syncthreads();

        uint32_t sa = sbase + (c & (NSTG - 1)) * STG;
        uint32_t sb = sa + A_BYTES;

        #pragma unroll
        for (int s = 0; s < 4; s++) {               // 4 x k16 steps
            const uint32_t c0 = ((2 * s)     ^ g) * 16 + t * 4;
            const uint32_t c1 = ((2 * s + 1) ^ g) * 16 + t * 4;
            uint32_t af[4][4], bf[8][2];
            #pragma unroll
            for (int i = 0; i < 4; i++) {
                uint32_t r0 = sa + (wm * 64 + i * 16 + g) * 128;
                af[i][0] = ldsu(r0 + c0);
                af[i][1] = ldsu(r0 + 8 * 128 + c0);
                af[i][2] = ldsu(r0 + c1);
                af[i][3] = ldsu(r0 + 8 * 128 + c1);
            }
            #pragma unroll
            for (int j = 0; j < 8; j++) {
                uint32_t rbb = sb + (wn * 64 + j * 8 + g) * 128;
                bf[j][0] = ldsu(rbb + c0);
                bf[j][1] = ldsu(rbb + c1);
            }
            #pragma unroll
            for (int i = 0; i < 4; i++) {
                #pragma unroll
                for (int j = 0; j < 8; j++) {
                    asm volatile(
                        "mma.sync.aligned.m16n8k16.row.col.f32.f16.f16.f32 "
                        "{%0,%1,%2,%3}, {%4,%5,%6,%7}, {%8,%9}, {%0,%1,%2,%3};\n"
                        : "+f"(acc[i][j][0]), "+f"(acc[i][j][1]),
                          "+f"(acc[i][j][2]), "+f"(acc[i][j][3])
                        : "r"(af[i][0]), "r"(af[i][1]),
                          "r"(af[i][2]), "r"(af[i][3]),
                          "r"(bf[j][0]), "r"(bf[j][1]));
                }
            }
        }
        __syncthreads();
    }

    // Epilogue: direct fp32 stores.
    float* Cb = C + (size_t)b * NDIM * MDIM;
    #pragma unroll
    for (int i = 0; i < 4; i++) {
        int row = by * TM + wm * 64 + i * 16 + g;
        #pragma unroll
        for (int j = 0; j < 8; j++) {
            int col = bx * TN + wn * 64 + j * 8 + 2 * t;
            *(float2*)(Cb + (size_t)row * MDIM + col) =
                make_float2(acc[i][j][0], acc[i][j][1]);
            *(float2*)(Cb + (size_t)(row + 8) * MDIM + col) =
                make_float2(acc[i][j][2], acc[i][j][3]);
        }
    }
}

extern "C" void kernel_launch(void* const* d_in, const int* in_sizes, int n_in,
                              void* d_out, int out_size) {
    const float* mat0 = (const float*)d_in[0];   // [8, 2048, 1024]
    const float* mat1 = (const float*)d_in[1];   // [8, 2048, 1024]
    float* out = (float*)d_out;                  // [8, 2048, 2048]
    cudaFuncSetAttribute(bmm_f16_v4,
                         cudaFuncAttributeMaxDynamicSharedMemorySize, SMEM_BYTES);
    dim3 grid(MDIM / TN, NDIM / TM, NB);         // (8, 16, 8)
    bmm_f16_v4<<<grid, 256, SMEM_BYTES>>>(mat0, mat1, out);
}

// round 6
// speedup vs baseline: 2.5775x; 2.5775x over previous
#include <cuda_runtime.h>
#include <cuda_fp16.h>
#include <cstdint>

// Batched C[b,n,m] = sum_e A[b,n,e] * B[b,m,e]
// b=8, n=m=2048, e=1024, fp32 in/out.
// v6: v2 structure (cp.async fp32 smem, 3-stage, 256 thr, 128x256 tile,
// 64x64 warp tiles) but consumed as fp16 m16n8k16 (fp32 accum).
// Fragment regs built by ld.shared.v2.f32 + cvt.rn.f16x2.

#define TM 128
#define TN 256
#define BK 32
#define NSTG 3
#define EDIM 1024
#define NDIM 2048
#define MDIM 2048
#define NB 8
#define NCHUNK (EDIM / BK)
#define A_BYTES (TM * BK * 4)           // 16384
#define B_BYTES (TN * BK * 4)           // 32768
#define STG (A_BYTES + B_BYTES)         // 49152
#define SMEM_BYTES (NSTG * STG)         // 147456

__device__ __forceinline__ uint32_t packf2(float lo, float hi) {
    uint32_t r;
    asm("cvt.rn.f16x2.f32 %0, %1, %2;" : "=r"(r) : "f"(hi), "f"(lo));
    return r;   // lower 16 bits = lo (first k), upper = hi (second k)
}
__device__ __forceinline__ float2 lds64(uint32_t a) {
    float2 v;
    asm volatile("ld.shared.v2.f32 {%0,%1}, [%2];"
                 : "=f"(v.x), "=f"(v.y) : "r"(a));
    return v;
}
__device__ __forceinline__ uint32_t ldpack(uint32_t a) {
    float2 v = lds64(a);
    return packf2(v.x, v.y);
}
__device__ __forceinline__ void cp16(uint32_t dst, const float* src) {
    asm volatile("cp.async.cg.shared.global [%0], [%1], 16;"
                 :: "r"(dst), "l"(src) : "memory");
}

// Per-thread: 4 A-lines + 8 B-lines of 16B per chunk.
// Swizzle: 16B-chunk column XOR (row & 7)  -> conflict-free fragment LDS.
__device__ __forceinline__ void issue_chunk(uint32_t sbase, const float* Ab,
                                            const float* Bb, int chunk,
                                            int lr, int lc) {
    uint32_t st = sbase + (chunk % NSTG) * STG;
    #pragma unroll
    for (int i = 0; i < 4; i++) {
        int row = lr + 32 * i;
        cp16(st + row * 128 + ((lc ^ (row & 7)) * 16),
             Ab + (size_t)row * EDIM + chunk * BK + lc * 4);
    }
    #pragma unroll
    for (int i = 0; i < 8; i++) {
        int row = lr + 32 * i;
        cp16(st + A_BYTES + row * 128 + ((lc ^ (row & 7)) * 16),
             Bb + (size_t)row * EDIM + chunk * BK + lc * 4);
    }
    asm volatile("cp.async.commit_group;" ::: "memory");
}

__global__ __launch_bounds__(256, 1)
void bmm_f16_v6(const float* __restrict__ A, const float* __restrict__ B,
                float* __restrict__ C) {
    extern __shared__ char smem[];
    uint32_t sbase;
    asm("{ .reg .u64 t; cvta.to.shared.u64 t, %1; cvt.u32.u64 %0, t; }"
        : "=r"(sbase) : "l"(smem));

    const int tid  = threadIdx.x;
    const int warp = tid >> 5;
    const int lane = tid & 31;
    const int wm   = warp & 1;        // 2 row blocks of 64
    const int wn   = warp >> 1;       // 4 col blocks of 64
    const int g    = lane >> 2;       // groupID 0..7
    const int t    = lane & 3;        // thread-in-group

    const int b = blockIdx.z, by = blockIdx.y, bx = blockIdx.x;
    const float* Ab = A + ((size_t)b * NDIM + (size_t)by * TM) * EDIM;
    const float* Bb = B + ((size_t)b * MDIM + (size_t)bx * TN) * EDIM;

    const int lr = tid >> 3;          // 0..31
    const int lc = tid & 7;           // 16B chunk 0..7

    float acc[4][8][4];
    #pragma unroll
    for (int i = 0; i < 4; i++)
        #pragma unroll
        for (int j = 0; j < 8; j++)
            #pragma unroll
            for (int r = 0; r < 4; r++) acc[i][j][r] = 0.f;

    issue_chunk(sbase, Ab, Bb, 0, lr, lc);
    issue_chunk(sbase, Ab, Bb, 1, lr, lc);

    for (int c = 0; c < NCHUNK; c++) {
        asm volatile("cp.async.wait_group 1;" ::: "memory");
        __syncthreads();
        if (c + 2 < NCHUNK)
            issue_chunk(sbase, Ab, Bb, c + 2, lr, lc);
        else
            asm volatile("cp.async.commit_group;" ::: "memory");

        uint32_t sa = sbase + (c % NSTG) * STG;
        uint32_t sb = sa + A_BYTES;

        #pragma unroll
        for (int s = 0; s < 2; s++) {              // 2 x k16 steps per BK=32
            // byte offsets within a 128B row (pre-swizzle):
            //   lo: k = 16s + 2t      -> off 64s + 8t
            //   hi: k = 16s + 8 + 2t  -> off 64s + 32 + 8t
            const uint32_t o_lo = (((4 * s +     (t >> 1)) ^ g) * 16) + 8 * (t & 1);
            const uint32_t o_hi = (((4 * s + 2 + (t >> 1)) ^ g) * 16) + 8 * (t & 1);

            uint32_t bf[8][2];
            #pragma unroll
            for (int j = 0; j < 8; j++) {
                uint32_t rb = sb + (wn * 64 + j * 8 + g) * 128;
                bf[j][0] = ldpack(rb + o_lo);
                bf[j][1] = ldpack(rb + o_hi);
            }
            #pragma unroll
            for (int i = 0; i < 4; i++) {
                uint32_t r0 = sa + (wm * 64 + i * 16 + g) * 128;
                uint32_t r8 = r0 + 8 * 128;
                uint32_t a0 = ldpack(r0 + o_lo);
                uint32_t a1 = ldpack(r8 + o_lo);
                uint32_t a2 = ldpack(r0 + o_hi);
                uint32_t a3 = ldpack(r8 + o_hi);
                #pragma unroll
                for (int j = 0; j < 8; j++) {
                    asm volatile(
                        "mma.sync.aligned.m16n8k16.row.col.f32.f16.f16.f32 "
                        "{%0,%1,%2,%3}, {%4,%5,%6,%7}, {%8,%9}, {%0,%1,%2,%3};\n"
                        : "+f"(acc[i][j][0]), "+f"(acc[i][j][1]),
                          "+f"(acc[i][j][2]), "+f"(acc[i][j][3])
                        : "r"(a0), "r"(a1), "r"(a2), "r"(a3),
                          "r"(bf[j][0]), "r"(bf[j][1]));
                }
            }
        }
    }

    // Epilogue: direct fp32 stores.
    float* Cb = C + (size_t)b * NDIM * MDIM;
    #pragma unroll
    for (int i = 0; i < 4; i++) {
        int row = by * TM + wm * 64 + i * 16 + g;
        #pragma unroll
        for (int j = 0; j < 8; j++) {
            int col = bx * TN + wn * 64 + j * 8 + 2 * t;
            *(float2*)(Cb + (size_t)row * MDIM + col) =
                make_float2(acc[i][j][0], acc[i][j][1]);
            *(float2*)(Cb + (size_t)(row + 8) * MDIM + col) =
                make_float2(acc[i][j][2], acc[i][j][3]);
        }
    }
}

extern "C" void kernel_launch(void* const* d_in, const int* in_sizes, int n_in,
                              void* d_out, int out_size) {
    const float* mat0 = (const float*)d_in[0];   // [8, 2048, 1024]
    const float* mat1 = (const float*)d_in[1];   // [8, 2048, 1024]
    float* out = (float*)d_out;                  // [8, 2048, 2048]
    cudaFuncSetAttribute(bmm_f16_v6,
                         cudaFuncAttributeMaxDynamicSharedMemorySize, SMEM_BYTES);
    dim3 grid(MDIM / TN, NDIM / TM, NB);         // (8, 16, 8)
    bmm_f16_v6<<<grid, 256, SMEM_BYTES>>>(mat0, mat1, out);
}

// round 7
// speedup vs baseline: 4.0933x; 1.5881x over previous
#include <cuda_runtime.h>
#include <cuda_fp16.h>
#include <cstdint>

// Batched C[b,n,m] = sum_e A[b,n,e] * B[b,m,e]
// b=8, n=m=2048, e=1024, fp32 in/out.
// v7: pre-kernel converts A,B fp32 -> fp16 into __device__ scratch (HBM-bound,
// ~35us). GEMM: pure fp16 pipeline — cp.async fp16 smem, ldmatrix.x4 fragment
// loads, mma.sync m16n8k16 (fp32 accum). 128x256 CTA tile, 256 thr, 64x64 warp
// tiles, BK=64 halfs, 3-stage ring, XOR-swizzled 128B rows.

#define TM 128
#define TN 256
#define BKH 64                   // halfs per chunk -> 128B rows
#define NSTG 3
#define EDIM 1024
#define NDIM 2048
#define MDIM 2048
#define NB 8
#define NCHUNK (EDIM / BKH)      // 16
#define A_BYTES (TM * BKH * 2)   // 16384
#define B_BYTES (TN * BKH * 2)   // 32768
#define STG (A_BYTES + B_BYTES)  // 49152
#define SMEM_BYTES (NSTG * STG)  // 147456

#define NELEM (NB * NDIM * EDIM)         // 16777216 per tensor
__device__ uint4 g_Ah[NELEM / 8];        // fp16 scratch, 16B-aligned
__device__ uint4 g_Bh[NELEM / 8];

// ---- conversion pre-kernel: 8 fp32 -> 8 fp16 per thread-iter ----
__global__ void __launch_bounds__(256)
cvt_f32_f16(const float4* __restrict__ src, uint4* __restrict__ dst, int n8) {
    int i = blockIdx.x * blockDim.x + threadIdx.x;
    int stride = gridDim.x * blockDim.x;
    for (; i < n8; i += stride) {
        float4 v0 = src[2 * i];
        float4 v1 = src[2 * i + 1];
        uint4 o;
        asm("cvt.rn.f16x2.f32 %0, %1, %2;" : "=r"(o.x) : "f"(v0.y), "f"(v0.x));
        asm("cvt.rn.f16x2.f32 %0, %1, %2;" : "=r"(o.y) : "f"(v0.w), "f"(v0.z));
        asm("cvt.rn.f16x2.f32 %0, %1, %2;" : "=r"(o.z) : "f"(v1.y), "f"(v1.x));
        asm("cvt.rn.f16x2.f32 %0, %1, %2;" : "=r"(o.w) : "f"(v1.w), "f"(v1.z));
        dst[i] = o;
    }
}

__device__ __forceinline__ void cp16(uint32_t dst, const __half* src) {
    asm volatile("cp.async.cg.shared.global [%0], [%1], 16;"
                 :: "r"(dst), "l"(src) : "memory");
}
__device__ __forceinline__ void ldsm4(uint32_t& r0, uint32_t& r1,
                                      uint32_t& r2, uint32_t& r3, uint32_t a) {
    asm volatile("ldmatrix.sync.aligned.m8n8.x4.shared.b16 {%0,%1,%2,%3}, [%4];"
                 : "=r"(r0), "=r"(r1), "=r"(r2), "=r"(r3) : "r"(a));
}

// Per-thread per chunk: 4 A-lines + 8 B-lines of 16B.
// Swizzle: 16B-chunk column XOR (row & 7).
__device__ __forceinline__ void issue_chunk(uint32_t sbase, const __half* Ab,
                                            const __half* Bb, int chunk,
                                            int lr, int lc) {
    uint32_t st = sbase + (chunk % NSTG) * STG;
    const int k0 = chunk * BKH + lc * 8;
    #pragma unroll
    for (int i = 0; i < 4; i++) {
        int row = lr + 32 * i;
        cp16(st + row * 128 + ((lc ^ (row & 7)) * 16),
             Ab + (size_t)row * EDIM + k0);
    }
    #pragma unroll
    for (int i = 0; i < 8; i++) {
        int row = lr + 32 * i;
        cp16(st + A_BYTES + row * 128 + ((lc ^ (row & 7)) * 16),
             Bb + (size_t)row * EDIM + k0);
    }
    asm volatile("cp.async.commit_group;" ::: "memory");
}

__global__ __launch_bounds__(256, 1)
void bmm_f16_v7(float* __restrict__ C) {
    extern __shared__ char smem[];
    uint32_t sbase;
    asm("{ .reg .u64 t; cvta.to.shared.u64 t, %1; cvt.u32.u64 %0, t; }"
        : "=r"(sbase) : "l"(smem));

    const int tid  = threadIdx.x;
    const int warp = tid >> 5;
    const int lane = tid & 31;
    const int wm   = warp & 1;        // 2 row blocks of 64
    const int wn   = warp >> 1;       // 4 col blocks of 64
    const int g    = lane >> 2;
    const int t    = lane & 3;

    const int b = blockIdx.z, by = blockIdx.y, bx = blockIdx.x;
    const __half* Ab = (const __half*)g_Ah + ((size_t)b * NDIM + (size_t)by * TM) * EDIM;
    const __half* Bb = (const __half*)g_Bh + ((size_t)b * MDIM + (size_t)bx * TN) * EDIM;

    const int lr = tid >> 3;          // 0..31
    const int lc = tid & 7;           // 16B chunk 0..7

    // ldmatrix lane-address components
    const int aRowB = wm * 64 + (lane & 15);                  // + i*16
    const int aHi   = lane >> 4;                              // k8 select
    const int bRowB = wn * 64 + (lane & 7) + ((lane >> 4) & 1) * 8;  // + j2*16
    const int bHi   = (lane >> 3) & 1;                        // k8 select

    float acc[4][8][4];
    #pragma unroll
    for (int i = 0; i < 4; i++)
        #pragma unroll
        for (int j = 0; j < 8; j++)
            #pragma unroll
            for (int r = 0; r < 4; r++) acc[i][j][r] = 0.f;

    issue_chunk(sbase, Ab, Bb, 0, lr, lc);
    issue_chunk(sbase, Ab, Bb, 1, lr, lc);

    for (int c = 0; c < NCHUNK; c++) {
        asm volatile("cp.async.wait_group 1;" ::: "memory");
        __syncthreads();
        if (c + 2 < NCHUNK)
            issue_chunk(sbase, Ab, Bb, c + 2, lr, lc);
        else
            asm volatile("cp.async.commit_group;" ::: "memory");

        uint32_t sa = sbase + (c % NSTG) * STG;
        uint32_t sb = sa + A_BYTES;

        #pragma unroll
        for (int s = 0; s < 4; s++) {             // 4 x k16 steps per BK=64
            // B fragments: 4 ldmatrix.x4 -> 8 n-blocks x {b0,b1}
            uint32_t bf[4][4];
            #pragma unroll
            for (int j2 = 0; j2 < 4; j2++) {
                int row = bRowB + j2 * 16;
                uint32_t addr = sb + row * 128 +
                                (((2 * s + bHi) ^ (row & 7)) * 16);
                ldsm4(bf[j2][0], bf[j2][1], bf[j2][2], bf[j2][3], addr);
            }
            #pragma unroll
            for (int i = 0; i < 4; i++) {
                int row = aRowB + i * 16;
                uint32_t addr = sa + row * 128 +
                                (((2 * s + aHi) ^ (row & 7)) * 16);
                uint32_t a0, a1, a2, a3;
                ldsm4(a0, a1, a2, a3, addr);
                #pragma unroll
                for (int j2 = 0; j2 < 4; j2++) {
                    asm volatile(
                        "mma.sync.aligned.m16n8k16.row.col.f32.f16.f16.f32 "
                        "{%0,%1,%2,%3}, {%4,%5,%6,%7}, {%8,%9}, {%0,%1,%2,%3};\n"
                        : "+f"(acc[i][2*j2][0]), "+f"(acc[i][2*j2][1]),
                          "+f"(acc[i][2*j2][2]), "+f"(acc[i][2*j2][3])
                        : "r"(a0), "r"(a1), "r"(a2), "r"(a3),
                          "r"(bf[j2][0]), "r"(bf[j2][1]));
                    asm volatile(
                        "mma.sync.aligned.m16n8k16.row.col.f32.f16.f16.f32 "
                        "{%0,%1,%2,%3}, {%4,%5,%6,%7}, {%8,%9}, {%0,%1,%2,%3};\n"
                        : "+f"(acc[i][2*j2+1][0]), "+f"(acc[i][2*j2+1][1]),
                          "+f"(acc[i][2*j2+1][2]), "+f"(acc[i][2*j2+1][3])
                        : "r"(a0), "r"(a1), "r"(a2), "r"(a3),
                          "r"(bf[j2][2]), "r"(bf[j2][3]));
                }
            }
        }
    }

    // Epilogue: direct fp32 stores.
    float* Cb = C + (size_t)b * NDIM * MDIM;
    #pragma unroll
    for (int i = 0; i < 4; i++) {
        int row = by * TM + wm * 64 + i * 16 + g;
        #pragma unroll
        for (int j = 0; j < 8; j++) {
            int col = bx * TN + wn * 64 + j * 8 + 2 * t;
            *(float2*)(Cb + (size_t)row * MDIM + col) =
                make_float2(acc[i][j][0], acc[i][j][1]);
            *(float2*)(Cb + (size_t)(row + 8) * MDIM + col) =
                make_float2(acc[i][j][2], acc[i][j][3]);
        }
    }
}

extern "C" void kernel_launch(void* const* d_in, const int* in_sizes, int n_in,
                              void* d_out, int out_size) {
    const float* mat0 = (const float*)d_in[0];   // [8, 2048, 1024]
    const float* mat1 = (const float*)d_in[1];   // [8, 2048, 1024]
    float* out = (float*)d_out;                  // [8, 2048, 2048]

    uint4* gA; uint4* gB;
    cudaGetSymbolAddress((void**)&gA, g_Ah);
    cudaGetSymbolAddress((void**)&gB, g_Bh);

    const int n8 = NELEM / 8;                    // 2097152
    cvt_f32_f16<<<2048, 256>>>((const float4*)mat0, gA, n8);
    cvt_f32_f16<<<2048, 256>>>((const float4*)mat1, gB, n8);

    cudaFuncSetAttribute(bmm_f16_v7,
                         cudaFuncAttributeMaxDynamicSharedMemorySize, SMEM_BYTES);
    dim3 grid(MDIM / TN, NDIM / TM, NB);         // (8, 16, 8)
    bmm_f16_v7<<<grid, 256, SMEM_BYTES>>>(out);
}

// round 8
// speedup vs baseline: 4.1814x; 1.0215x over previous
#include <cuda_runtime.h>
#include <cuda_fp16.h>
#include <cstdint>

// Batched C[b,n,m] = sum_e A[b,n,e] * B[b,m,e]
// b=8, n=m=2048, e=1024, fp32 in/out.
// v8: single cvt pre-kernel (both tensors) fp32->fp16 scratch; GEMM pure fp16:
// cp.async fp16 smem (4-stage ring), ldmatrix.x4 with k-step fragment
// double-buffering, mma.sync m16n8k16 fp32-accum. 128x256 tile, 256 thr,
// 64x64 warp tiles, BK=64 halfs, XOR-swizzled 128B rows.

#define TM 128
#define TN 256
#define BKH 64
#define NSTG 4
#define EDIM 1024
#define NDIM 2048
#define MDIM 2048
#define NB 8
#define NCHUNK (EDIM / BKH)      // 16
#define A_BYTES (TM * BKH * 2)   // 16384
#define B_BYTES (TN * BKH * 2)   // 32768
#define STG (A_BYTES + B_BYTES)  // 49152
#define SMEM_BYTES (NSTG * STG)  // 196608

#define NELEM (NB * NDIM * EDIM)         // 16777216 per tensor
__device__ uint4 g_Ah[NELEM / 8];
__device__ uint4 g_Bh[NELEM / 8];

// ---- conversion pre-kernel: grid.y selects tensor ----
__global__ void __launch_bounds__(256)
cvt_f32_f16(const float4* __restrict__ s0, uint4* __restrict__ d0,
            const float4* __restrict__ s1, uint4* __restrict__ d1, int n8) {
    const float4* src = blockIdx.y ? s1 : s0;
    uint4* dst = blockIdx.y ? d1 : d0;
    int i = blockIdx.x * blockDim.x + threadIdx.x;
    int stride = gridDim.x * blockDim.x;
    for (; i < n8; i += stride) {
        float4 v0 = src[2 * i];
        float4 v1 = src[2 * i + 1];
        uint4 o;
        asm("cvt.rn.f16x2.f32 %0, %1, %2;" : "=r"(o.x) : "f"(v0.y), "f"(v0.x));
        asm("cvt.rn.f16x2.f32 %0, %1, %2;" : "=r"(o.y) : "f"(v0.w), "f"(v0.z));
        asm("cvt.rn.f16x2.f32 %0, %1, %2;" : "=r"(o.z) : "f"(v1.y), "f"(v1.x));
        asm("cvt.rn.f16x2.f32 %0, %1, %2;" : "=r"(o.w) : "f"(v1.w), "f"(v1.z));
        dst[i] = o;
    }
}

__device__ __forceinline__ void cp16(uint32_t dst, const __half* src) {
    asm volatile("cp.async.cg.shared.global [%0], [%1], 16;"
                 :: "r"(dst), "l"(src) : "memory");
}
__device__ __forceinline__ void ldsm4(uint32_t& r0, uint32_t& r1,
                                      uint32_t& r2, uint32_t& r3, uint32_t a) {
    asm volatile("ldmatrix.sync.aligned.m8n8.x4.shared.b16 {%0,%1,%2,%3}, [%4];"
                 : "=r"(r0), "=r"(r1), "=r"(r2), "=r"(r3) : "r"(a));
}

__device__ __forceinline__ void issue_chunk(uint32_t sbase, const __half* Ab,
                                            const __half* Bb, int chunk,
                                            int lr, int lc) {
    uint32_t st = sbase + (chunk & (NSTG - 1)) * STG;
    const int k0 = chunk * BKH + lc * 8;
    #pragma unroll
    for (int i = 0; i < 4; i++) {
        int row = lr + 32 * i;
        cp16(st + row * 128 + ((lc ^ (row & 7)) * 16),
             Ab + (size_t)row * EDIM + k0);
    }
    #pragma unroll
    for (int i = 0; i < 8; i++) {
        int row = lr + 32 * i;
        cp16(st + A_BYTES + row * 128 + ((lc ^ (row & 7)) * 16),
             Bb + (size_t)row * EDIM + k0);
    }
    asm volatile("cp.async.commit_group;" ::: "memory");
}

__global__ __launch_bounds__(256, 1)
void bmm_f16_v8(float* __restrict__ C) {
    extern __shared__ char smem[];
    uint32_t sbase;
    asm("{ .reg .u64 t; cvta.to.shared.u64 t, %1; cvt.u32.u64 %0, t; }"
        : "=r"(sbase) : "l"(smem));

    const int tid  = threadIdx.x;
    const int warp = tid >> 5;
    const int lane = tid & 31;
    const int wm   = warp & 1;
    const int wn   = warp >> 1;
    const int g    = lane >> 2;
    const int t    = lane & 3;

    const int b = blockIdx.z, by = blockIdx.y, bx = blockIdx.x;
    const __half* Ab = (const __half*)g_Ah + ((size_t)b * NDIM + (size_t)by * TM) * EDIM;
    const __half* Bb = (const __half*)g_Bh + ((size_t)b * MDIM + (size_t)bx * TN) * EDIM;

    const int lr = tid >> 3;
    const int lc = tid & 7;

    // ldmatrix lane-address components
    const int aRowB = wm * 64 + (lane & 15);
    const int aHi   = lane >> 4;
    const int bRowB = wn * 64 + (lane & 7) + ((lane >> 4) & 1) * 8;
    const int bHi   = (lane >> 3) & 1;

    float acc[4][8][4];
    #pragma unroll
    for (int i = 0; i < 4; i++)
        #pragma unroll
        for (int j = 0; j < 8; j++)
            #pragma unroll
            for (int r = 0; r < 4; r++) acc[i][j][r] = 0.f;

    issue_chunk(sbase, Ab, Bb, 0, lr, lc);
    issue_chunk(sbase, Ab, Bb, 1, lr, lc);
    issue_chunk(sbase, Ab, Bb, 2, lr, lc);

    uint32_t af[2][4][4], bf[2][4][4];

    #define LOAD_FRAGS(buf, sa, sb, s) do {                                   \
        _Pragma("unroll")                                                     \
        for (int j2 = 0; j2 < 4; j2++) {                                      \
            int row = bRowB + j2 * 16;                                        \
            ldsm4(bf[buf][j2][0], bf[buf][j2][1],                             \
                  bf[buf][j2][2], bf[buf][j2][3],                             \
                  (sb) + row * 128 + ((((2*(s)) + bHi) ^ (row & 7)) * 16));   \
        }                                                                     \
        _Pragma("unroll")                                                     \
        for (int i = 0; i < 4; i++) {                                         \
            int row = aRowB + i * 16;                                         \
            ldsm4(af[buf][i][0], af[buf][i][1],                               \
                  af[buf][i][2], af[buf][i][3],                               \
                  (sa) + row * 128 + ((((2*(s)) + aHi) ^ (row & 7)) * 16));   \
        }                                                                     \
    } while (0)

    for (int c = 0; c < NCHUNK; c++) {
        asm volatile("cp.async.wait_group 2;" ::: "memory");
        __syncthreads();
        if (c + 3 < NCHUNK)
            issue_chunk(sbase, Ab, Bb, c + 3, lr, lc);
        else
            asm volatile("cp.async.commit_group;" ::: "memory");

        uint32_t sa = sbase + (c & (NSTG - 1)) * STG;
        uint32_t sb = sa + A_BYTES;

        LOAD_FRAGS(0, sa, sb, 0);
        #pragma unroll
        for (int s = 0; s < 4; s++) {
            const int cur = s & 1;
            if (s < 3) LOAD_FRAGS(!cur ? 1 : 0, sa, sb, s + 1);
            #pragma unroll
            for (int i = 0; i < 4; i++) {
                #pragma unroll
                for (int j2 = 0; j2 < 4; j2++) {
                    asm volatile(
                        "mma.sync.aligned.m16n8k16.row.col.f32.f16.f16.f32 "
                        "{%0,%1,%2,%3}, {%4,%5,%6,%7}, {%8,%9}, {%0,%1,%2,%3};\n"
                        : "+f"(acc[i][2*j2][0]), "+f"(acc[i][2*j2][1]),
                          "+f"(acc[i][2*j2][2]), "+f"(acc[i][2*j2][3])
                        : "r"(af[cur][i][0]), "r"(af[cur][i][1]),
                          "r"(af[cur][i][2]), "r"(af[cur][i][3]),
                          "r"(bf[cur][j2][0]), "r"(bf[cur][j2][1]));
                    asm volatile(
                        "mma.sync.aligned.m16n8k16.row.col.f32.f16.f16.f32 "
                        "{%0,%1,%2,%3}, {%4,%5,%6,%7}, {%8,%9}, {%0,%1,%2,%3};\n"
                        : "+f"(acc[i][2*j2+1][0]), "+f"(acc[i][2*j2+1][1]),
                          "+f"(acc[i][2*j2+1][2]), "+f"(acc[i][2*j2+1][3])
                        : "r"(af[cur][i][0]), "r"(af[cur][i][1]),
                          "r"(af[cur][i][2]), "r"(af[cur][i][3]),
                          "r"(bf[cur][j2][2]), "r"(bf[cur][j2][3]));
                }
            }
        }
    }

    float* Cb = C + (size_t)b * NDIM * MDIM;
    #pragma unroll
    for (int i = 0; i < 4; i++) {
        int row = by * TM + wm * 64 + i * 16 + g;
        #pragma unroll
        for (int j = 0; j < 8; j++) {
            int col = bx * TN + wn * 64 + j * 8 + 2 * t;
            *(float2*)(Cb + (size_t)row * MDIM + col) =
                make_float2(acc[i][j][0], acc[i][j][1]);
            *(float2*)(Cb + (size_t)(row + 8) * MDIM + col) =
                make_float2(acc[i][j][2], acc[i][j][3]);
        }
    }
}

extern "C" void kernel_launch(void* const* d_in, const int* in_sizes, int n_in,
                              void* d_out, int out_size) {
    const float* mat0 = (const float*)d_in[0];
    const float* mat1 = (const float*)d_in[1];
    float* out = (float*)d_out;

    uint4* gA; uint4* gB;
    cudaGetSymbolAddress((void**)&gA, g_Ah);
    cudaGetSymbolAddress((void**)&gB, g_Bh);

    const int n8 = NELEM / 8;
    dim3 cgrid(2048, 2, 1);
    cvt_f32_f16<<<cgrid, 256>>>((const float4*)mat0, gA,
                                (const float4*)mat1, gB, n8);

    cudaFuncSetAttribute(bmm_f16_v8,
                         cudaFuncAttributeMaxDynamicSharedMemorySize, SMEM_BYTES);
    dim3 grid(MDIM / TN, NDIM / TM, NB);
    bmm_f16_v8<<<grid, 256, SMEM_BYTES>>>(out);
}

// round 9
// speedup vs baseline: 4.2496x; 1.0163x over previous
#include <cuda_runtime.h>
#include <cuda_fp16.h>
#include <cstdint>

// Batched C[b,n,m] = sum_e A[b,n,e] * B[b,m,e]
// b=8, n=m=2048, e=1024, fp32 in/out.
// v9: cvt pre-kernel fp32->fp16 scratch; GEMM pure fp16: cp.async 4-stage
// ring, ldmatrix.x4, mma.sync m16n8k16. 128x256 CTA tile, 512 threads,
// 16 warps (4x4) of 32x64 tiles, single-buffered fragments (occupancy hides
// LDSM latency: 4 warps/SMSP).

#define TM 128
#define TN 256
#define BKH 64
#define NSTG 4
#define EDIM 1024
#define NDIM 2048
#define MDIM 2048
#define NB 8
#define NCHUNK (EDIM / BKH)      // 16
#define A_BYTES (TM * BKH * 2)   // 16384
#define B_BYTES (TN * BKH * 2)   // 32768
#define STG (A_BYTES + B_BYTES)  // 49152
#define SMEM_BYTES (NSTG * STG)  // 196608

#define NELEM (NB * NDIM * EDIM)
__device__ uint4 g_Ah[NELEM / 8];
__device__ uint4 g_Bh[NELEM / 8];

__global__ void __launch_bounds__(256)
cvt_f32_f16(const float4* __restrict__ s0, uint4* __restrict__ d0,
            const float4* __restrict__ s1, uint4* __restrict__ d1, int n8) {
    const float4* src = blockIdx.y ? s1 : s0;
    uint4* dst = blockIdx.y ? d1 : d0;
    int i = blockIdx.x * blockDim.x + threadIdx.x;
    int stride = gridDim.x * blockDim.x;
    for (; i < n8; i += stride) {
        float4 v0 = src[2 * i];
        float4 v1 = src[2 * i + 1];
        uint4 o;
        asm("cvt.rn.f16x2.f32 %0, %1, %2;" : "=r"(o.x) : "f"(v0.y), "f"(v0.x));
        asm("cvt.rn.f16x2.f32 %0, %1, %2;" : "=r"(o.y) : "f"(v0.w), "f"(v0.z));
        asm("cvt.rn.f16x2.f32 %0, %1, %2;" : "=r"(o.z) : "f"(v1.y), "f"(v1.x));
        asm("cvt.rn.f16x2.f32 %0, %1, %2;" : "=r"(o.w) : "f"(v1.w), "f"(v1.z));
        dst[i] = o;
    }
}

__device__ __forceinline__ void cp16(uint32_t dst, const __half* src) {
    asm volatile("cp.async.cg.shared.global [%0], [%1], 16;"
                 :: "r"(dst), "l"(src) : "memory");
}
__device__ __forceinline__ void ldsm4(uint32_t& r0, uint32_t& r1,
                                      uint32_t& r2, uint32_t& r3, uint32_t a) {
    asm volatile("ldmatrix.sync.aligned.m8n8.x4.shared.b16 {%0,%1,%2,%3}, [%4];"
                 : "=r"(r0), "=r"(r1), "=r"(r2), "=r"(r3) : "r"(a));
}

// 512 threads: per thread 2 A-lines + 4 B-lines of 16B per chunk.
__device__ __forceinline__ void issue_chunk(uint32_t sbase, const __half* Ab,
                                            const __half* Bb, int chunk,
                                            int lr, int lc) {
    uint32_t st = sbase + (chunk & (NSTG - 1)) * STG;
    const int k0 = chunk * BKH + lc * 8;
    #pragma unroll
    for (int i = 0; i < 2; i++) {
        int row = lr + 64 * i;
        cp16(st + row * 128 + ((lc ^ (row & 7)) * 16),
             Ab + (size_t)row * EDIM + k0);
    }
    #pragma unroll
    for (int i = 0; i < 4; i++) {
        int row = lr + 64 * i;
        cp16(st + A_BYTES + row * 128 + ((lc ^ (row & 7)) * 16),
             Bb + (size_t)row * EDIM + k0);
    }
    asm volatile("cp.async.commit_group;" ::: "memory");
}

__global__ __launch_bounds__(512, 1)
void bmm_f16_v9(float* __restrict__ C) {
    extern __shared__ char smem[];
    uint32_t sbase;
    asm("{ .reg .u64 t; cvta.to.shared.u64 t, %1; cvt.u32.u64 %0, t; }"
        : "=r"(sbase) : "l"(smem));

    const int tid  = threadIdx.x;
    const int warp = tid >> 5;
    const int lane = tid & 31;
    const int wm   = warp & 3;        // 4 row blocks of 32
    const int wn   = warp >> 2;       // 4 col blocks of 64
    const int g    = lane >> 2;
    const int t    = lane & 3;

    const int b = blockIdx.z, by = blockIdx.y, bx = blockIdx.x;
    const __half* Ab = (const __half*)g_Ah + ((size_t)b * NDIM + (size_t)by * TM) * EDIM;
    const __half* Bb = (const __half*)g_Bh + ((size_t)b * MDIM + (size_t)bx * TN) * EDIM;

    const int lr = tid >> 3;          // 0..63
    const int lc = tid & 7;

    const int aRowB = wm * 32 + (lane & 15);                  // + i*16
    const int aHi   = lane >> 4;
    const int bRowB = wn * 64 + (lane & 7) + ((lane >> 4) & 1) * 8;  // + j2*16
    const int bHi   = (lane >> 3) & 1;

    float acc[2][8][4];
    #pragma unroll
    for (int i = 0; i < 2; i++)
        #pragma unroll
        for (int j = 0; j < 8; j++)
            #pragma unroll
            for (int r = 0; r < 4; r++) acc[i][j][r] = 0.f;

    issue_chunk(sbase, Ab, Bb, 0, lr, lc);
    issue_chunk(sbase, Ab, Bb, 1, lr, lc);
    issue_chunk(sbase, Ab, Bb, 2, lr, lc);

    for (int c = 0; c < NCHUNK; c++) {
        asm volatile("cp.async.wait_group 2;" ::: "memory");
        __syncthreads();
        if (c + 3 < NCHUNK)
            issue_chunk(sbase, Ab, Bb, c + 3, lr, lc);
        else
            asm volatile("cp.async.commit_group;" ::: "memory");

        uint32_t sa = sbase + (c & (NSTG - 1)) * STG;
        uint32_t sb = sa + A_BYTES;

        #pragma unroll
        for (int s = 0; s < 4; s++) {
            uint32_t bf[4][4];
            #pragma unroll
            for (int j2 = 0; j2 < 4; j2++) {
                int row = bRowB + j2 * 16;
                ldsm4(bf[j2][0], bf[j2][1], bf[j2][2], bf[j2][3],
                      sb + row * 128 + (((2 * s + bHi) ^ (row & 7)) * 16));
            }
            #pragma unroll
            for (int i = 0; i < 2; i++) {
                int row = aRowB + i * 16;
                uint32_t a0, a1, a2, a3;
                ldsm4(a0, a1, a2, a3,
                      sa + row * 128 + (((2 * s + aHi) ^ (row & 7)) * 16));
                #pragma unroll
                for (int j2 = 0; j2 < 4; j2++) {
                    asm volatile(
                        "mma.sync.aligned.m16n8k16.row.col.f32.f16.f16.f32 "
                        "{%0,%1,%2,%3}, {%4,%5,%6,%7}, {%8,%9}, {%0,%1,%2,%3};\n"
                        : "+f"(acc[i][2*j2][0]), "+f"(acc[i][2*j2][1]),
                          "+f"(acc[i][2*j2][2]), "+f"(acc[i][2*j2][3])
                        : "r"(a0), "r"(a1), "r"(a2), "r"(a3),
                          "r"(bf[j2][0]), "r"(bf[j2][1]));
                    asm volatile(
                        "mma.sync.aligned.m16n8k16.row.col.f32.f16.f16.f32 "
                        "{%0,%1,%2,%3}, {%4,%5,%6,%7}, {%8,%9}, {%0,%1,%2,%3};\n"
                        : "+f"(acc[i][2*j2+1][0]), "+f"(acc[i][2*j2+1][1]),
                          "+f"(acc[i][2*j2+1][2]), "+f"(acc[i][2*j2+1][3])
                        : "r"(a0), "r"(a1), "r"(a2), "r"(a3),
                          "r"(bf[j2][2]), "r"(bf[j2][3]));
                }
            }
        }
    }

    float* Cb = C + (size_t)b * NDIM * MDIM;
    #pragma unroll
    for (int i = 0; i < 2; i++) {
        int row = by * TM + wm * 32 + i * 16 + g;
        #pragma unroll
        for (int j = 0; j < 8; j++) {
            int col = bx * TN + wn * 64 + j * 8 + 2 * t;
            *(float2*)(Cb + (size_t)row * MDIM + col) =
                make_float2(acc[i][j][0], acc[i][j][1]);
            *(float2*)(Cb + (size_t)(row + 8) * MDIM + col) =
                make_float2(acc[i][j][2], acc[i][j][3]);
        }
    }
}

extern "C" void kernel_launch(void* const* d_in, const int* in_sizes, int n_in,
                              void* d_out, int out_size) {
    const float* mat0 = (const float*)d_in[0];
    const float* mat1 = (const float*)d_in[1];
    float* out = (float*)d_out;

    uint4* gA; uint4* gB;
    cudaGetSymbolAddress((void**)&gA, g_Ah);
    cudaGetSymbolAddress((void**)&gB, g_Bh);

    const int n8 = NELEM / 8;
    dim3 cgrid(2048, 2, 1);
    cvt_f32_f16<<<cgrid, 256>>>((const float4*)mat0, gA,
                                (const float4*)mat1, gB, n8);

    cudaFuncSetAttribute(bmm_f16_v9,
                         cudaFuncAttributeMaxDynamicSharedMemorySize, SMEM_BYTES);
    dim3 grid(MDIM / TN, NDIM / TM, NB);
    bmm_f16_v9<<<grid, 512, SMEM_BYTES>>>(out);
}